// round 8
// baseline (speedup 1.0000x reference)
#include <cuda_runtime.h>
#include <math.h>
#include <stdint.h>

// ---------------------------------------------------------------------------
// GATNE forward v3.1 — role-pure kernels (v3 + shfl-mask fix in k_gather):
//   k_scan   : one CTA, two stable partitions (idx<NU for gemm; type for trans)
//   k_gather : warp per (b,t), streaming neighbor gather+sum -> g_nsum (gmem)
//   k_trans  : type-partitioned; nte = nsum . U[type], 2 rows/warp share U
//              reads; fused attention -> g_agg[B][40]
//   k_gemm2  : out = [userF | agg | textF] @ [userW ; transW ; textW],
//              fused L2-normalize
// ---------------------------------------------------------------------------

#define EMB       200
#define EMBU      20
#define TEXT_DIM  768
#define USER_DIM  32
#define NSLOT     10
#define B_MAX     4096

#define GBM       16
#define GBK       40
#define GTH       160

// ------------------------- device scratch ----------------------------------
__device__ int    g_rowmap[B_MAX];   // partition by idx<NU (users first)
__device__ int    g_tmap[B_MAX];     // partition by type (type0 first)
__device__ int    g_nuser;
__device__ int    g_ntype0;
__device__ float  g_agg[B_MAX * 40];
__device__ float4 g_nsum4[B_MAX * 2 * (TEXT_DIM / 4)];   // [B][2][192] float4

// ------------------------- scan: two partitions, one pass -------------------
__global__ __launch_bounds__(1024, 1) void k_scan(
    const int* __restrict__ indices, const int* __restrict__ types,
    int B, int NU)
{
    __shared__ int wsU[32], wsT[32];
    int tid = threadIdx.x;
    int lane = tid & 31, w = tid >> 5;
    int b0 = tid * 4;

    int idxv[4], tyv[4];
    int cu = 0, ct = 0;
#pragma unroll
    for (int j = 0; j < 4; j++) {
        int b = b0 + j;
        if (b < B) {
            idxv[j] = indices[b];
            tyv[j]  = types[b];
            cu += (idxv[j] < NU);
            ct += (tyv[j] == 0);
        }
    }
    int xu = cu, xt = ct;
    for (int o = 1; o < 32; o <<= 1) {
        int yu = __shfl_up_sync(0xffffffffu, xu, o);
        int yt = __shfl_up_sync(0xffffffffu, xt, o);
        if (lane >= o) { xu += yu; xt += yt; }
    }
    if (lane == 31) { wsU[w] = xu; wsT[w] = xt; }
    __syncthreads();
    int baseU = 0, baseT = 0, totU = 0, totT = 0;
    for (int i = 0; i < 32; i++) {
        if (i < w) { baseU += wsU[i]; baseT += wsT[i]; }
        totU += wsU[i]; totT += wsT[i];
    }
    int uRun = (xu - cu) + baseU;
    int tRun = (xt - ct) + baseT;
#pragma unroll
    for (int j = 0; j < 4; j++) {
        int b = b0 + j;
        if (b >= B) break;
        if (idxv[j] < NU) g_rowmap[uRun++] = b;
        else              g_rowmap[totU + (b - uRun)] = b;
        if (tyv[j] == 0)  g_tmap[tRun++] = b;
        else              g_tmap[totT + (b - tRun)] = b;
    }
    if (tid == 0) { g_nuser = totU; g_ntype0 = totT; }
}

// ------------------------- gather: warp per (b,t) ----------------------------
__global__ __launch_bounds__(256) void k_gather(
    const int*   __restrict__ train_types,
    const int*   __restrict__ node_neigh,
    const float* __restrict__ neigh_features,
    int B)
{
    int tid  = threadIdx.x;
    int wid  = tid >> 5;
    int lane = tid & 31;
    int gw   = blockIdx.x * 8 + wid;      // global warp id
    int b    = gw >> 1;
    int t    = gw & 1;
    if (b >= B) return;

    int ty = train_types[b];
    int nn_l = 0;
    if (lane < NSLOT)
        nn_l = node_neigh[(size_t)(b * 2 + t) * NSLOT + lane];

    const float4* nf4 = (const float4*)neigh_features;   // rows of 192 float4
    float4* dst = g_nsum4 + (size_t)(b * 2 + t) * 192;

    if (ty == 1) {
        // F = 768 : 6 chunks of 32 float4s
#pragma unroll 2
        for (int c = 0; c < 6; c++) {
            int k4 = c * 32 + lane;
            float4 acc = make_float4(0.f, 0.f, 0.f, 0.f);
#pragma unroll
            for (int s = 0; s < NSLOT; s++) {
                int idx = __shfl_sync(0xffffffffu, nn_l, s);
                float4 v = nf4[(size_t)idx * 192 + k4];
                acc.x += v.x; acc.y += v.y; acc.z += v.z; acc.w += v.w;
            }
            dst[k4] = acc;
        }
    } else {
        // F = 32 : lanes 0..7 each one float4. ALL lanes participate in the
        // shuffle (source lanes 8,9 must be in the mask); only lanes<8 load.
        float4 acc = make_float4(0.f, 0.f, 0.f, 0.f);
#pragma unroll
        for (int s = 0; s < NSLOT; s++) {
            int idx = __shfl_sync(0xffffffffu, nn_l, s);
            if (lane < 8) {
                float4 v = nf4[(size_t)idx * 192 + lane];
                acc.x += v.x; acc.y += v.y; acc.z += v.z; acc.w += v.w;
            }
        }
        if (lane < 8) dst[lane] = acc;
    }
}

// ------------------------- transform + attention -----------------------------
// Grid: [0,T) -> type-0 tiles, [T,2T) -> type-1 tiles (T = ceil(B/16)).
// 16 rows per CTA, 8 warps, 2 rows per warp (shared U reads).
__global__ __launch_bounds__(256, 1) void k_trans(
    const float* __restrict__ tweet_u,
    const float* __restrict__ user_u,
    const float* __restrict__ s1,
    const float* __restrict__ s2,
    int B, int T)
{
    extern __shared__ float sm[];
    float* U2  = sm;                        // [2][F][20]
    float* nte = U2 + 2 * TEXT_DIM * EMBU;  // [16][40]
    int*  srow = (int*)(nte + 16 * 40);     // [16]

    int tid  = threadIdx.x;
    int wid  = tid >> 5;
    int lane = tid & 31;

    int ty   = (blockIdx.x >= T) ? 1 : 0;
    int tile = ty ? (blockIdx.x - T) : blockIdx.x;
    int n0   = g_ntype0;
    int base = ty ? n0 : 0;
    int cnt  = ty ? (B - n0) : n0;
    int m0   = tile * 16;
    if (m0 >= cnt) return;

    int F = ty ? TEXT_DIM : USER_DIM;

    // load U[type] (both t) into smem
    {
        int cnt4 = (2 * F * EMBU) / 4;
        const float4* src = (const float4*)(ty ? tweet_u : user_u);
        float4* d = (float4*)U2;
        for (int i = tid; i < cnt4; i += 256) d[i] = src[i];
    }
    if (tid < 16) {
        int mm = m0 + tid; if (mm > cnt - 1) mm = cnt - 1;
        srow[tid] = g_tmap[base + mm];
    }
    __syncthreads();

    // warp w: rows 2w, 2w+1
    {
        int i0 = 2 * wid, i1 = 2 * wid + 1;
        int b0 = srow[i0], b1 = srow[i1];
        const float* ns = (const float*)g_nsum4;

        for (int t = 0; t < 2; t++) {
            float accA[EMBU], accB[EMBU];
#pragma unroll
            for (int u = 0; u < EMBU; u++) { accA[u] = 0.f; accB[u] = 0.f; }
            const float* ns0 = ns + (size_t)(b0 * 2 + t) * TEXT_DIM;
            const float* ns1 = ns + (size_t)(b1 * 2 + t) * TEXT_DIM;
            const float* Ut  = U2 + (size_t)t * F * EMBU;
            for (int k = lane; k < F; k += 32) {
                float a0 = ns0[k];
                float a1 = ns1[k];
                const float4* Urow = (const float4*)(Ut + k * EMBU);
#pragma unroll
                for (int q = 0; q < 5; q++) {
                    float4 uv = Urow[q];
                    accA[q*4+0] += a0 * uv.x; accB[q*4+0] += a1 * uv.x;
                    accA[q*4+1] += a0 * uv.y; accB[q*4+1] += a1 * uv.y;
                    accA[q*4+2] += a0 * uv.z; accB[q*4+2] += a1 * uv.z;
                    accA[q*4+3] += a0 * uv.w; accB[q*4+3] += a1 * uv.w;
                }
            }
#pragma unroll
            for (int u = 0; u < EMBU; u++) {
                float rA = accA[u], rB = accB[u];
                for (int o = 16; o; o >>= 1) {
                    rA += __shfl_xor_sync(0xffffffffu, rA, o);
                    rB += __shfl_xor_sync(0xffffffffu, rB, o);
                }
                if (lane == 0) {
                    nte[i0 * 40 + t * EMBU + u] = rA;
                    nte[i1 * 40 + t * EMBU + u] = rB;
                }
            }
        }
    }
    __syncthreads();

    // attention: warp handles rows wid and wid+8
    const float* S1 = s1 + ty * (EMBU * EMBU);
    const float* S2 = s2 + ty * EMBU;
    for (int g = wid; g < 16; g += 8) {
        if (m0 + g >= cnt) continue;
        int b = srow[g];
        float sc[2];
#pragma unroll
        for (int t = 0; t < 2; t++) {
            float h = 0.f;
            if (lane < EMBU) {
#pragma unroll
                for (int u = 0; u < EMBU; u++)
                    h += nte[g * 40 + t * EMBU + u] * S1[u * EMBU + lane];
                h = tanhf(h) * S2[lane];
            }
            for (int o = 16; o; o >>= 1) h += __shfl_xor_sync(0xffffffffu, h, o);
            sc[t] = h;
        }
        float m  = fmaxf(sc[0], sc[1]);
        float e0 = expf(sc[0] - m);
        float e1 = expf(sc[1] - m);
        float inv = 1.f / (e0 + e1);
        float a0 = e0 * inv, a1 = e1 * inv;
        for (int l = lane; l < 40; l += 32) {
            float v = 0.f;
            if ((l / EMBU) == ty) {
                int u = l - (l / EMBU) * EMBU;
                v = a0 * nte[g * 40 + u] + a1 * nte[g * 40 + EMBU + u];
            }
            g_agg[(size_t)b * 40 + l] = v;
        }
    }
}

// ------------------------- GEMM + fused normalize ---------------------------
__global__ __launch_bounds__(GTH, 4) void k_gemm2(
    float* __restrict__ out,
    const int*   __restrict__ indices,
    const float* __restrict__ user_features,
    const float* __restrict__ text_features,
    const float* __restrict__ user_embed,
    const float* __restrict__ text_embed,
    const float* __restrict__ trans_w,
    int B, int NU)
{
    __shared__ float As[GBK][GBM + 4];
    __shared__ float Bs[GBK][EMB];
    __shared__ float sOut[GBM][EMB];
    __shared__ float snrm[GBM];
    __shared__ int   srow[GBM], sidx[GBM];

    int half = gridDim.x >> 1;
    int cls  = (blockIdx.x >= half) ? 1 : 0;
    int tile = cls ? (blockIdx.x - half) : blockIdx.x;
    int nuser = g_nuser;
    int base = cls ? nuser : 0;
    int cnt  = cls ? (B - nuser) : nuser;
    int m0   = tile * GBM;
    if (m0 >= cnt) return;

    int tid = threadIdx.x;
    if (tid < GBM) {
        int mm = m0 + tid; if (mm > cnt - 1) mm = cnt - 1;
        int b = g_rowmap[base + mm];
        srow[tid] = b;
        sidx[tid] = indices[b];
    }
    __syncthreads();

    int ntiles = cls ? 21 : 2;   // user rows: only k<80 is nonzero
    float acc[4][5];
#pragma unroll
    for (int i = 0; i < 4; i++)
#pragma unroll
        for (int j = 0; j < 5; j++) acc[i][j] = 0.f;

    int rowid = tid / 40;
    int colid = tid - rowid * 40;

    for (int kt = 0; kt < ntiles; kt++) {
        int k0 = kt * GBK;
        for (int i = tid; i < GBM * GBK; i += GTH) {
            int m = i / GBK, k = i - m * GBK;
            int kk = k0 + k;
            int b = srow[m], idx = sidx[m];
            float v;
            if (kk < USER_DIM)
                v = (idx < NU) ? user_features[(size_t)idx * USER_DIM + kk] : 0.f;
            else if (kk < 72)
                v = g_agg[(size_t)b * 40 + (kk - USER_DIM)];
            else
                v = (idx < NU) ? 0.f
                               : text_features[(size_t)(idx - NU) * TEXT_DIM + (kk - 72)];
            As[k][m] = v;
        }
        for (int i = tid; i < GBK * (EMB / 2); i += GTH) {
            int k  = i / (EMB / 2);
            int j2 = i - k * (EMB / 2);
            int kk = k0 + k;
            const float* src;
            if (kk < USER_DIM)      src = user_embed + (size_t)kk * EMB;
            else if (kk < 72)       src = trans_w + (size_t)(kk - USER_DIM) * EMB;
            else                    src = text_embed + (size_t)(kk - 72) * EMB;
            *(float2*)&Bs[k][j2 * 2] = *(const float2*)(src + j2 * 2);
        }
        __syncthreads();

#pragma unroll 4
        for (int k = 0; k < GBK; k++) {
            float4 av = *(const float4*)&As[k][rowid * 4];
            float a[4] = {av.x, av.y, av.z, av.w};
            float bb[5];
#pragma unroll
            for (int j = 0; j < 5; j++) bb[j] = Bs[k][colid * 5 + j];
#pragma unroll
            for (int i = 0; i < 4; i++)
#pragma unroll
                for (int j = 0; j < 5; j++)
                    acc[i][j] += a[i] * bb[j];
        }
        __syncthreads();
    }

#pragma unroll
    for (int i = 0; i < 4; i++)
#pragma unroll
        for (int j = 0; j < 5; j++)
            sOut[rowid * 4 + i][colid * 5 + j] = acc[i][j];
    __syncthreads();

    int wid = tid >> 5, lane = tid & 31;
    for (int m = wid; m < GBM; m += 5) {
        float ss = 0.f;
        for (int j = lane; j < EMB; j += 32) { float x = sOut[m][j]; ss += x * x; }
        for (int o = 16; o; o >>= 1) ss += __shfl_xor_sync(0xffffffffu, ss, o);
        if (lane == 0) snrm[m] = 1.f / fmaxf(sqrtf(ss), 1e-12f);
    }
    __syncthreads();

    int mlim = cnt - m0; if (mlim > GBM) mlim = GBM;
    for (int i = tid; i < GBM * EMB; i += GTH) {
        int m = i / EMB, j = i - m * EMB;
        if (m < mlim)
            out[(size_t)srow[m] * EMB + j] = sOut[m][j] * snrm[m];
    }
}

// ------------------------- launch ------------------------------------------
extern "C" void kernel_launch(void* const* d_in, const int* in_sizes, int n_in,
                              void* d_out, int out_size)
{
    const int*   train_types    = (const int*)d_in[1];
    const int*   node_neigh     = (const int*)d_in[2];
    const int*   indices        = (const int*)d_in[3];
    const float* user_features  = (const float*)d_in[4];
    const float* text_features  = (const float*)d_in[5];
    const float* neigh_features = (const float*)d_in[6];
    const float* text_embed     = (const float*)d_in[7];
    const float* user_embed     = (const float*)d_in[8];
    const float* tweet_u        = (const float*)d_in[9];
    const float* user_u         = (const float*)d_in[10];
    const float* trans_w        = (const float*)d_in[11];
    const float* s1             = (const float*)d_in[12];
    const float* s2             = (const float*)d_in[13];

    int B  = in_sizes[3];
    int NU = in_sizes[4] / USER_DIM;
    float* out = (float*)d_out;

    const int trans_smem = (2 * TEXT_DIM * EMBU + 16 * 40) * 4 + 16 * 4;
    cudaFuncSetAttribute(k_trans, cudaFuncAttributeMaxDynamicSharedMemorySize,
                         trans_smem);

    k_scan<<<1, 1024>>>(indices, train_types, B, NU);

    int gwarps = B * 2;
    k_gather<<<(gwarps + 7) / 8, 256>>>(train_types, node_neigh,
                                        neigh_features, B);

    int T = (B + 15) / 16;
    k_trans<<<2 * T, 256, trans_smem>>>(tweet_u, user_u, s1, s2, B, T);

    int gtiles = (B + GBM - 1) / GBM;
    k_gemm2<<<2 * gtiles, GTH>>>(out, indices, user_features, text_features,
                                 user_embed, text_embed, trans_w, B, NU);
}

// round 9
// speedup vs baseline: 2.8417x; 2.8417x over previous
#include <cuda_runtime.h>
#include <math.h>
#include <stdint.h>

// ---------------------------------------------------------------------------
// GATNE forward v4:
//   k_scan   : one CTA, two stable partitions (idx<NU ; type)
//   k_gather : warp per (b,t), streaming neighbor gather+sum -> g_nsum4
//   k_trans  : type-partitioned transform + attention -> g_agg[B][40]
//   k_gemm3  : 320-thread CTAs, BM=32 x BN=200; user class: tiles 0-1 +
//              fused normalize; text class: K-split x7 -> partials
//   k_reduce : sum 7 partials per text row, normalize, write
// ---------------------------------------------------------------------------

#define EMB       200
#define EMBU      20
#define TEXT_DIM  768
#define USER_DIM  32
#define NSLOT     10
#define B_MAX     4096
#define NCHUNK    7            // text K-split: 21 tiles = 7 chunks x 3

// ------------------------- device scratch ----------------------------------
__device__ int    g_rowmap[B_MAX];   // partition by idx<NU (users first)
__device__ int    g_tmap[B_MAX];     // partition by type (type0 first)
__device__ int    g_nuser;
__device__ int    g_ntype0;
__device__ float  g_agg[B_MAX * 40];
__device__ float4 g_nsum4[B_MAX * 2 * (TEXT_DIM / 4)];   // [B][2][192] float4
__device__ float  g_part[(size_t)NCHUNK * B_MAX * EMB];  // text partials

// ------------------------- scan: two partitions, one pass -------------------
__global__ __launch_bounds__(1024, 1) void k_scan(
    const int* __restrict__ indices, const int* __restrict__ types,
    int B, int NU)
{
    __shared__ int wsU[32], wsT[32];
    int tid = threadIdx.x;
    int lane = tid & 31, w = tid >> 5;
    int b0 = tid * 4;

    int idxv[4], tyv[4];
    int cu = 0, ct = 0;
#pragma unroll
    for (int j = 0; j < 4; j++) {
        int b = b0 + j;
        if (b < B) {
            idxv[j] = indices[b];
            tyv[j]  = types[b];
            cu += (idxv[j] < NU);
            ct += (tyv[j] == 0);
        }
    }
    int xu = cu, xt = ct;
    for (int o = 1; o < 32; o <<= 1) {
        int yu = __shfl_up_sync(0xffffffffu, xu, o);
        int yt = __shfl_up_sync(0xffffffffu, xt, o);
        if (lane >= o) { xu += yu; xt += yt; }
    }
    if (lane == 31) { wsU[w] = xu; wsT[w] = xt; }
    __syncthreads();
    int baseU = 0, baseT = 0, totU = 0, totT = 0;
    for (int i = 0; i < 32; i++) {
        if (i < w) { baseU += wsU[i]; baseT += wsT[i]; }
        totU += wsU[i]; totT += wsT[i];
    }
    int uRun = (xu - cu) + baseU;
    int tRun = (xt - ct) + baseT;
#pragma unroll
    for (int j = 0; j < 4; j++) {
        int b = b0 + j;
        if (b >= B) break;
        if (idxv[j] < NU) g_rowmap[uRun++] = b;
        else              g_rowmap[totU + (b - uRun)] = b;
        if (tyv[j] == 0)  g_tmap[tRun++] = b;
        else              g_tmap[totT + (b - tRun)] = b;
    }
    if (tid == 0) { g_nuser = totU; g_ntype0 = totT; }
}

// ------------------------- gather: warp per (b,t) ----------------------------
__global__ __launch_bounds__(256) void k_gather(
    const int*   __restrict__ train_types,
    const int*   __restrict__ node_neigh,
    const float* __restrict__ neigh_features,
    int B)
{
    int tid  = threadIdx.x;
    int wid  = tid >> 5;
    int lane = tid & 31;
    int gw   = blockIdx.x * 8 + wid;
    int b    = gw >> 1;
    int t    = gw & 1;
    if (b >= B) return;

    int ty = train_types[b];
    int nn_l = 0;
    if (lane < NSLOT)
        nn_l = node_neigh[(size_t)(b * 2 + t) * NSLOT + lane];

    const float4* nf4 = (const float4*)neigh_features;
    float4* dst = g_nsum4 + (size_t)(b * 2 + t) * 192;

    if (ty == 1) {
#pragma unroll 2
        for (int c = 0; c < 6; c++) {
            int k4 = c * 32 + lane;
            float4 acc = make_float4(0.f, 0.f, 0.f, 0.f);
#pragma unroll
            for (int s = 0; s < NSLOT; s++) {
                int idx = __shfl_sync(0xffffffffu, nn_l, s);
                float4 v = nf4[(size_t)idx * 192 + k4];
                acc.x += v.x; acc.y += v.y; acc.z += v.z; acc.w += v.w;
            }
            dst[k4] = acc;
        }
    } else {
        float4 acc = make_float4(0.f, 0.f, 0.f, 0.f);
#pragma unroll
        for (int s = 0; s < NSLOT; s++) {
            int idx = __shfl_sync(0xffffffffu, nn_l, s);
            if (lane < 8) {
                float4 v = nf4[(size_t)idx * 192 + lane];
                acc.x += v.x; acc.y += v.y; acc.z += v.z; acc.w += v.w;
            }
        }
        if (lane < 8) dst[lane] = acc;
    }
}

// ------------------------- transform + attention -----------------------------
__global__ __launch_bounds__(256, 1) void k_trans(
    const float* __restrict__ tweet_u,
    const float* __restrict__ user_u,
    const float* __restrict__ s1,
    const float* __restrict__ s2,
    int B, int T)
{
    extern __shared__ float sm[];
    float* U2  = sm;
    float* nte = U2 + 2 * TEXT_DIM * EMBU;
    int*  srow = (int*)(nte + 16 * 40);

    int tid  = threadIdx.x;
    int wid  = tid >> 5;
    int lane = tid & 31;

    int ty   = (blockIdx.x >= T) ? 1 : 0;
    int tile = ty ? (blockIdx.x - T) : blockIdx.x;
    int n0   = g_ntype0;
    int base = ty ? n0 : 0;
    int cnt  = ty ? (B - n0) : n0;
    int m0   = tile * 16;
    if (m0 >= cnt) return;

    int F = ty ? TEXT_DIM : USER_DIM;

    {
        int cnt4 = (2 * F * EMBU) / 4;
        const float4* src = (const float4*)(ty ? tweet_u : user_u);
        float4* d = (float4*)U2;
        for (int i = tid; i < cnt4; i += 256) d[i] = src[i];
    }
    if (tid < 16) {
        int mm = m0 + tid; if (mm > cnt - 1) mm = cnt - 1;
        srow[tid] = g_tmap[base + mm];
    }
    __syncthreads();

    {
        int i0 = 2 * wid, i1 = 2 * wid + 1;
        int b0 = srow[i0], b1 = srow[i1];
        const float* ns = (const float*)g_nsum4;

        for (int t = 0; t < 2; t++) {
            float accA[EMBU], accB[EMBU];
#pragma unroll
            for (int u = 0; u < EMBU; u++) { accA[u] = 0.f; accB[u] = 0.f; }
            const float* ns0 = ns + (size_t)(b0 * 2 + t) * TEXT_DIM;
            const float* ns1 = ns + (size_t)(b1 * 2 + t) * TEXT_DIM;
            const float* Ut  = U2 + (size_t)t * F * EMBU;
            for (int k = lane; k < F; k += 32) {
                float a0 = ns0[k];
                float a1 = ns1[k];
                const float4* Urow = (const float4*)(Ut + k * EMBU);
#pragma unroll
                for (int q = 0; q < 5; q++) {
                    float4 uv = Urow[q];
                    accA[q*4+0] += a0 * uv.x; accB[q*4+0] += a1 * uv.x;
                    accA[q*4+1] += a0 * uv.y; accB[q*4+1] += a1 * uv.y;
                    accA[q*4+2] += a0 * uv.z; accB[q*4+2] += a1 * uv.z;
                    accA[q*4+3] += a0 * uv.w; accB[q*4+3] += a1 * uv.w;
                }
            }
#pragma unroll
            for (int u = 0; u < EMBU; u++) {
                float rA = accA[u], rB = accB[u];
                for (int o = 16; o; o >>= 1) {
                    rA += __shfl_xor_sync(0xffffffffu, rA, o);
                    rB += __shfl_xor_sync(0xffffffffu, rB, o);
                }
                if (lane == 0) {
                    nte[i0 * 40 + t * EMBU + u] = rA;
                    nte[i1 * 40 + t * EMBU + u] = rB;
                }
            }
        }
    }
    __syncthreads();

    const float* S1 = s1 + ty * (EMBU * EMBU);
    const float* S2 = s2 + ty * EMBU;
    for (int g = wid; g < 16; g += 8) {
        if (m0 + g >= cnt) continue;
        int b = srow[g];
        float sc[2];
#pragma unroll
        for (int t = 0; t < 2; t++) {
            float h = 0.f;
            if (lane < EMBU) {
#pragma unroll
                for (int u = 0; u < EMBU; u++)
                    h += nte[g * 40 + t * EMBU + u] * S1[u * EMBU + lane];
                h = tanhf(h) * S2[lane];
            }
            for (int o = 16; o; o >>= 1) h += __shfl_xor_sync(0xffffffffu, h, o);
            sc[t] = h;
        }
        float m  = fmaxf(sc[0], sc[1]);
        float e0 = expf(sc[0] - m);
        float e1 = expf(sc[1] - m);
        float inv = 1.f / (e0 + e1);
        float a0 = e0 * inv, a1 = e1 * inv;
        for (int l = lane; l < 40; l += 32) {
            float v = 0.f;
            if ((l / EMBU) == ty) {
                int u = l - (l / EMBU) * EMBU;
                v = a0 * nte[g * 40 + u] + a1 * nte[g * 40 + EMBU + u];
            }
            g_agg[(size_t)b * 40 + l] = v;
        }
    }
}

// ------------------------- GEMM v3: BM=32 x BN=200, 320 threads --------------
// Grid: [0, utiles)                -> user class, tiles 0-1, fused normalize
//       [utiles, utiles+7*utiles)  -> text class, chunk = 3 tiles, partials
__global__ __launch_bounds__(320) void k_gemm3(
    float* __restrict__ out,
    const int*   __restrict__ indices,
    const float* __restrict__ user_features,
    const float* __restrict__ text_features,
    const float* __restrict__ user_embed,
    const float* __restrict__ text_embed,
    const float* __restrict__ trans_w,
    int B, int NU, int utiles)
{
    __shared__ __align__(16) float As[40][36];
    __shared__ __align__(16) float Bs[40][EMB];
    __shared__ float ssP[32][41];
    __shared__ float snrm[32];
    __shared__ int   srow[32], sidx[32];

    int bx = blockIdx.x;
    int cls, tm, chunk, kt0, ntk;
    if (bx < utiles) { cls = 0; tm = bx; chunk = 0; kt0 = 0; ntk = 2; }
    else {
        int r = bx - utiles;
        tm = r / NCHUNK; chunk = r - tm * NCHUNK;
        cls = 1; kt0 = chunk * 3; ntk = 3;
    }
    int nuser = g_nuser;
    int base  = cls ? nuser : 0;
    int cnt   = cls ? (B - nuser) : nuser;
    int m0    = tm * 32;
    if (m0 >= cnt) return;

    int tid = threadIdx.x;
    if (tid < 32) {
        int mm = m0 + tid; if (mm > cnt - 1) mm = cnt - 1;
        int b = g_rowmap[base + mm];
        srow[tid] = b;
        sidx[tid] = indices[b];
    }
    __syncthreads();

    int rg = tid / 40;             // 0..7 (4 rows each)
    int cg = tid - rg * 40;        // 0..39 (5 cols each)

    float acc[4][5];
#pragma unroll
    for (int i = 0; i < 4; i++)
#pragma unroll
        for (int j = 0; j < 5; j++) acc[i][j] = 0.f;

    for (int t = 0; t < ntk; t++) {
        int k0 = (kt0 + t) * 40;
        // A tile: 32 rows x 40 k
        for (int i = tid; i < 32 * 40; i += 320) {
            int m = i & 31, k = i >> 5;
            int kk = k0 + k;
            int b = srow[m], idx = sidx[m];
            float v;
            if (kk < USER_DIM)
                v = (idx < NU) ? user_features[(size_t)idx * USER_DIM + kk] : 0.f;
            else if (kk < 72)
                v = g_agg[(size_t)b * 40 + (kk - USER_DIM)];
            else
                v = (idx < NU) ? 0.f
                               : text_features[(size_t)(idx - NU) * TEXT_DIM + (kk - 72)];
            As[k][m] = v;
        }
        // B tile: 40 x 200, float4
        for (int i = tid; i < 40 * (EMB / 4); i += 320) {
            int k  = i / (EMB / 4);
            int j4 = i - k * (EMB / 4);
            int kk = k0 + k;
            const float* src;
            if (kk < USER_DIM)      src = user_embed + (size_t)kk * EMB;
            else if (kk < 72)       src = trans_w + (size_t)(kk - USER_DIM) * EMB;
            else                    src = text_embed + (size_t)(kk - 72) * EMB;
            ((float4*)&Bs[k][0])[j4] = ((const float4*)src)[j4];
        }
        __syncthreads();

#pragma unroll 8
        for (int k = 0; k < 40; k++) {
            float4 av = *(const float4*)&As[k][rg * 4];
            float a[4] = {av.x, av.y, av.z, av.w};
            float bb[5];
#pragma unroll
            for (int j = 0; j < 5; j++) bb[j] = Bs[k][cg * 5 + j];
#pragma unroll
            for (int i = 0; i < 4; i++)
#pragma unroll
                for (int j = 0; j < 5; j++)
                    acc[i][j] += a[i] * bb[j];
        }
        __syncthreads();
    }

    if (cls == 0) {
        // fused normalize + direct write
#pragma unroll
        for (int r = 0; r < 4; r++) {
            float s = 0.f;
#pragma unroll
            for (int j = 0; j < 5; j++) s += acc[r][j] * acc[r][j];
            ssP[rg * 4 + r][cg] = s;
        }
        __syncthreads();
        if (tid < 32) {
            float s = 0.f;
            for (int c = 0; c < 40; c++) s += ssP[tid][c];
            snrm[tid] = 1.f / fmaxf(sqrtf(s), 1e-12f);
        }
        __syncthreads();
#pragma unroll
        for (int r = 0; r < 4; r++) {
            int m = rg * 4 + r;
            if (m0 + m < cnt) {
                float sc = snrm[m];
                float* o = out + (size_t)srow[m] * EMB + cg * 5;
#pragma unroll
                for (int j = 0; j < 5; j++) o[j] = acc[r][j] * sc;
            }
        }
    } else {
        // write partials (class-relative row index)
        float* pb = g_part + (size_t)chunk * B_MAX * EMB;
#pragma unroll
        for (int r = 0; r < 4; r++) {
            int m = rg * 4 + r;
            int mr = m0 + m;
            if (mr < cnt) {
                float* p = pb + (size_t)mr * EMB + cg * 5;
#pragma unroll
                for (int j = 0; j < 5; j++) p[j] = acc[r][j];
            }
        }
    }
}

// ------------------------- reduce partials + normalize -----------------------
__global__ __launch_bounds__(256) void k_reduce(float* __restrict__ out, int B)
{
    __shared__ float ws[8];
    int i = blockIdx.x;
    int nuser = g_nuser;
    int ntext = B - nuser;
    if (i >= ntext) return;
    int b = g_rowmap[nuser + i];
    int tid = threadIdx.x;

    float v = 0.f;
    if (tid < EMB) {
#pragma unroll
        for (int c = 0; c < NCHUNK; c++)
            v += g_part[(size_t)c * B_MAX * EMB + (size_t)i * EMB + tid];
    }
    float s = v * v;
    for (int o = 16; o; o >>= 1) s += __shfl_xor_sync(0xffffffffu, s, o);
    if ((tid & 31) == 0) ws[tid >> 5] = s;
    __syncthreads();
    float tot = 0.f;
#pragma unroll
    for (int w = 0; w < 8; w++) tot += ws[w];
    float sc = 1.f / fmaxf(sqrtf(tot), 1e-12f);
    if (tid < EMB) out[(size_t)b * EMB + tid] = v * sc;
}

// ------------------------- launch ------------------------------------------
extern "C" void kernel_launch(void* const* d_in, const int* in_sizes, int n_in,
                              void* d_out, int out_size)
{
    const int*   train_types    = (const int*)d_in[1];
    const int*   node_neigh     = (const int*)d_in[2];
    const int*   indices        = (const int*)d_in[3];
    const float* user_features  = (const float*)d_in[4];
    const float* text_features  = (const float*)d_in[5];
    const float* neigh_features = (const float*)d_in[6];
    const float* text_embed     = (const float*)d_in[7];
    const float* user_embed     = (const float*)d_in[8];
    const float* tweet_u        = (const float*)d_in[9];
    const float* user_u         = (const float*)d_in[10];
    const float* trans_w        = (const float*)d_in[11];
    const float* s1             = (const float*)d_in[12];
    const float* s2             = (const float*)d_in[13];

    int B  = in_sizes[3];
    int NU = in_sizes[4] / USER_DIM;
    float* out = (float*)d_out;

    const int trans_smem = (2 * TEXT_DIM * EMBU + 16 * 40) * 4 + 16 * 4;
    cudaFuncSetAttribute(k_trans, cudaFuncAttributeMaxDynamicSharedMemorySize,
                         trans_smem);

    int gwarps = B * 2;
    k_gather<<<(gwarps + 7) / 8, 256>>>(train_types, node_neigh,
                                        neigh_features, B);

    k_scan<<<1, 1024>>>(indices, train_types, B, NU);

    int T = (B + 15) / 16;
    k_trans<<<2 * T, 256, trans_smem>>>(tweet_u, user_u, s1, s2, B, T);

    int utiles = (B + 31) / 32;
    k_gemm3<<<utiles * (1 + NCHUNK), 320>>>(out, indices, user_features,
                                            text_features, user_embed,
                                            text_embed, trans_w, B, NU, utiles);

    k_reduce<<<B, 256>>>(out, B);
}